// round 9
// baseline (speedup 1.0000x reference)
#include <cuda_runtime.h>
#include <cuda_bf16.h>
#include <math.h>
#include <stdint.h>

// Problem constants
#define BATCH 8
#define NPTS  8192
#define DIM   256
#define DOUT  512
#define MPTS  2048
#define KNN   16
#define RTOT  (BATCH * NPTS)   // 65536 rows
#define EPS   1e-5f

// ---------------------------------------------------------------------------
// Scratch
// ---------------------------------------------------------------------------
__device__ __align__(128) float d_h1  [(size_t)RTOT * DIM];
__device__ __align__(128) float d_h2  [(size_t)RTOT * DIM];
__device__ __align__(128) float d_hpos[(size_t)RTOT * DIM];
__device__ __align__(128) float d_hgeo[(size_t)RTOT * DIM];
__device__ __align__(128) float d_q   [(size_t)RTOT * DIM];
__device__ __align__(128) float d_k   [(size_t)RTOT * DIM];
__device__ __align__(128) float d_v   [(size_t)RTOT * DIM];
__device__ __align__(128) float d_s   [(size_t)RTOT * DIM];
__device__ __align__(128) float d_f   [(size_t)RTOT * DIM];
__device__ __align__(128) float d_g512[(size_t)RTOT * DOUT];
__device__ __align__(128) float d_wt  [14 * 256 * 256];

#define SLOT (256 * 256)

// ---------------------------------------------------------------------------
// helpers
// ---------------------------------------------------------------------------
__device__ __forceinline__ float f2tf32_rn(float v) {
    uint32_t u;
    asm("cvt.rna.tf32.f32 %0, %1;" : "=r"(u) : "f"(v));
    return __uint_as_float(u);
}

__device__ __forceinline__ void mma_tf32(float* c, const uint32_t* a, const uint32_t* b) {
    asm volatile(
        "mma.sync.aligned.m16n8k8.row.col.f32.tf32.tf32.f32 "
        "{%0,%1,%2,%3}, {%4,%5,%6,%7}, {%8,%9}, {%0,%1,%2,%3};"
        : "+f"(c[0]), "+f"(c[1]), "+f"(c[2]), "+f"(c[3])
        : "r"(a[0]), "r"(a[1]), "r"(a[2]), "r"(a[3]), "r"(b[0]), "r"(b[1]));
}

__device__ __forceinline__ uint32_t smem_u32(const void* p) {
    uint32_t a;
    asm("{ .reg .u64 t; cvta.to.shared.u64 t, %1; cvt.u32.u64 %0, t; }" : "=r"(a) : "l"(p));
    return a;
}

#define CP_ASYNC16(dst, src) \
    asm volatile("cp.async.cg.shared.global [%0], [%1], 16;" :: "r"(dst), "l"(src))
#define CP_COMMIT() asm volatile("cp.async.commit_group;")
template<int N> __device__ __forceinline__ void cp_wait() {
    asm volatile("cp.async.wait_group %0;" :: "n"(N));
}

#define LDSM_X4(r, addr) \
    asm volatile("ldmatrix.sync.aligned.m8n8.x4.shared.b16 {%0,%1,%2,%3}, [%4];" \
        : "=r"((r)[0]), "=r"((r)[1]), "=r"((r)[2]), "=r"((r)[3]) : "r"(addr))
#define LDSM_X2(r, addr) \
    asm volatile("ldmatrix.sync.aligned.m8n8.x2.shared.b16 {%0,%1}, [%2];" \
        : "=r"((r)[0]), "=r"((r)[1]) : "r"(addr))

// ---------------------------------------------------------------------------
// Batched weight transpose (rounded to tf32-rn at write)
// ---------------------------------------------------------------------------
__global__ __launch_bounds__(256) void transpose_all(
    const float* __restrict__ m1w2, const float* __restrict__ m2w2,
    const float* __restrict__ wq, const float* __restrict__ wk,
    const float* __restrict__ wv, const float* __restrict__ wo,
    const float* __restrict__ td, float* __restrict__ wt)
{
    __shared__ float t[32][33];
    const int z = blockIdx.z;
    const float* src;
    int srcN = 256, colOff = 0;
    float* dst;
    if (z < 12) {
        const int i = z / 6, j = z % 6;
        const size_t off = (size_t)i * SLOT;
        switch (j) {
            case 0: src = m1w2 + off; break;
            case 1: src = m2w2 + off; break;
            case 2: src = wq   + off; break;
            case 3: src = wk   + off; break;
            case 4: src = wv   + off; break;
            default: src = wo  + off; break;
        }
        dst = wt + (size_t)(i * 6 + j) * SLOT;
    } else {
        src = td; srcN = 512; colOff = (z - 12) * 256;
        dst = wt + (size_t)(12 + (z - 12)) * SLOT;
    }

    const int bx = blockIdx.x * 32;
    const int by = blockIdx.y * 32;
    const int tx = threadIdx.x & 31, ty = threadIdx.x >> 5;
#pragma unroll
    for (int i = ty; i < 32; i += 8)
        t[i][tx] = src[(size_t)(by + i) * srcN + colOff + bx + tx];
    __syncthreads();
#pragma unroll
    for (int i = ty; i < 32; i += 8)
        dst[(size_t)(bx + i) * 256 + by + tx] = f2tf32_rn(t[tx][i]);
}

// ---------------------------------------------------------------------------
// tf32 mma.sync GEMM, cp.async + ldmatrix.
// CTA tile 128x256, 512 threads (16 warps, 2 row x 8 col), warp tile 64x32.
// K chunks of 32 floats, 3-stage ring (48KB/stage = A16K + B32K), 1 CTA/SM.
// smem rows: row-major 32-float rows, 16B units XOR-swizzled by row&7.
// modes: 0 = +bias[c]+Add[r,c]  1 = *scale  2 = none  3 = relu(bn(acc+bias))
//        4 = dual q/k  5 = LN(Add + acc + bias) with g/b in bn_g/bn_b
// ---------------------------------------------------------------------------
#define STG_BYTES 49152                 // A 16KB + B 32KB
#define TC_SMEM_TOTAL (3 * STG_BYTES)   // 144KB

__global__ void __launch_bounds__(512, 1) tc_gemm(
    const float* __restrict__ A, const float* __restrict__ Wt,
    const float* __restrict__ bias, const float* __restrict__ Add,
    float* __restrict__ C, float* __restrict__ C2,
    int Nout, int mode, float scale,
    const float* __restrict__ bn_g, const float* __restrict__ bn_b,
    const float* __restrict__ bn_mean, const float* __restrict__ bn_var)
{
    extern __shared__ char smem[];
    const uint32_t sbase = smem_u32(smem);
    const int tid  = threadIdx.x;
    const int lane = tid & 31;
    const int wid  = tid >> 5;
    const int wr   = wid >> 3;       // 0..1 -> 64-row slab
    const int wc   = wid & 7;        // 0..7 -> 32-col slab

    const int blockRow = blockIdx.y * 128;
    const int blockCol = blockIdx.x * 256;

    const float* Abase = A  + (size_t)blockRow * 256;
    const float* Bbase = Wt + (size_t)blockCol * 256;

    // ---- cp.async loader ----
    // A: 1024 float4/chunk -> 2 per thread; B: 2048 float4/chunk -> 4 per thread
    int rowLA[2], qLA[2];
    uint32_t offLA[2];
#pragma unroll
    for (int i = 0; i < 2; i++) {
        const int idx = tid + i * 512;
        rowLA[i] = idx >> 3;
        qLA[i]   = idx & 7;
        offLA[i] = (uint32_t)rowLA[i] * 128u + (uint32_t)((qLA[i] ^ (rowLA[i] & 7)) * 16);
    }
    int rowLB[4], qLB[4];
    uint32_t offLB[4];
#pragma unroll
    for (int i = 0; i < 4; i++) {
        const int idx = tid + i * 512;
        rowLB[i] = idx >> 3;
        qLB[i]   = idx & 7;
        offLB[i] = (uint32_t)rowLB[i] * 128u + (uint32_t)((qLB[i] ^ (rowLB[i] & 7)) * 16);
    }

    auto issue_chunk = [&](int c, int s) {
        const int k0 = c * 32;
        const uint32_t ab = sbase + (uint32_t)s * STG_BYTES;
        const uint32_t bb = ab + 16384u;
#pragma unroll
        for (int i = 0; i < 2; i++)
            CP_ASYNC16(ab + offLA[i], Abase + (size_t)rowLA[i] * 256 + k0 + qLA[i] * 4);
#pragma unroll
        for (int i = 0; i < 4; i++)
            CP_ASYNC16(bb + offLB[i], Bbase + (size_t)rowLB[i] * 256 + k0 + qLB[i] * 4);
        CP_COMMIT();
    };

    // ---- ldmatrix addressing ----
    const int l7 = lane & 7;
    const int hA = lane >> 4;
    const int hB = (lane >> 3) & 1;
    uint32_t aOff[4], bOff[4];
#pragma unroll
    for (int t = 0; t < 4; t++) {
        const int rA = wr * 64 + t * 16 + ((lane >> 3) & 1) * 8 + l7;
        aOff[t] = (uint32_t)rA * 128u;
        const int rB = wc * 32 + t * 8 + l7;
        bOff[t] = (uint32_t)rB * 128u;
    }

    float acc[4][4][4];
#pragma unroll
    for (int i = 0; i < 4; i++)
#pragma unroll
        for (int j = 0; j < 4; j++)
#pragma unroll
            for (int e = 0; e < 4; e++) acc[i][j][e] = 0.f;

    auto compute = [&](int s) {
        const uint32_t sA = sbase + (uint32_t)s * STG_BYTES;
        const uint32_t sB = sA + 16384u;
#pragma unroll
        for (int kt = 0; kt < 4; kt++) {
            const uint32_t qa = (uint32_t)((((kt << 1) + hA) ^ l7) << 4);
            const uint32_t qb = (uint32_t)((((kt << 1) + hB) ^ l7) << 4);
            uint32_t aF[4][4], bF[4][2];
#pragma unroll
            for (int rt4 = 0; rt4 < 4; rt4++)
                LDSM_X4(aF[rt4], sA + aOff[rt4] + qa);
#pragma unroll
            for (int nt4 = 0; nt4 < 4; nt4++)
                LDSM_X2(bF[nt4], sB + bOff[nt4] + qb);
#pragma unroll
            for (int rt4 = 0; rt4 < 4; rt4++)
#pragma unroll
                for (int nt4 = 0; nt4 < 4; nt4++)
                    mma_tf32(acc[rt4][nt4], aF[rt4], bF[nt4]);
        }
    };

    issue_chunk(0, 0);
    issue_chunk(1, 1);
#pragma unroll
    for (int c = 0; c < 8; c++) {
        if (c == 7) cp_wait<0>(); else cp_wait<1>();
        __syncthreads();
        if (c + 2 < 8) issue_chunk(c + 2, (c + 2) % 3);
        compute(c % 3);
    }

    // ---- epilogue ----
    const int g   = lane >> 2;
    const int tig = lane & 3;

    if (mode == 5) {
        // LayerNorm(Add + acc + bias) over the full 256-col row in this CTA.
        float* part = (float*)smem;   // [128][8] partials (stage-0 region; free
                                      // of LDSM readers for stage 7%3=1)
        float mu[8];
        // pass 0: v = acc + bias + Add; row sums
#pragma unroll
        for (int rt4 = 0; rt4 < 4; rt4++) {
#pragma unroll
            for (int half = 0; half < 2; half++) {
                const int rl = wr * 64 + rt4 * 16 + g + half * 8;
                const int row = blockRow + rl;
                const float* Arow = Add + (size_t)row * 256;
                float s = 0.f;
#pragma unroll
                for (int nt4 = 0; nt4 < 4; nt4++) {
                    const int col = wc * 32 + nt4 * 8 + tig * 2;
                    float v0 = acc[rt4][nt4][half * 2 + 0] + bias[col] + Arow[col];
                    float v1 = acc[rt4][nt4][half * 2 + 1] + bias[col + 1] + Arow[col + 1];
                    acc[rt4][nt4][half * 2 + 0] = v0;
                    acc[rt4][nt4][half * 2 + 1] = v1;
                    s += v0 + v1;
                }
                s += __shfl_xor_sync(0xFFFFFFFFu, s, 1);
                s += __shfl_xor_sync(0xFFFFFFFFu, s, 2);
                if (tig == 0) part[rl * 8 + wc] = s;
            }
        }
        __syncthreads();
#pragma unroll
        for (int rt4 = 0; rt4 < 4; rt4++) {
#pragma unroll
            for (int half = 0; half < 2; half++) {
                const int rl = wr * 64 + rt4 * 16 + g + half * 8;
                float s = 0.f;
#pragma unroll
                for (int w = 0; w < 8; w++) s += part[rl * 8 + w];
                mu[rt4 * 2 + half] = s * (1.f / 256.f);
            }
        }
        __syncthreads();
        // pass 1: centered variance
#pragma unroll
        for (int rt4 = 0; rt4 < 4; rt4++) {
#pragma unroll
            for (int half = 0; half < 2; half++) {
                const int rl = wr * 64 + rt4 * 16 + g + half * 8;
                const float m = mu[rt4 * 2 + half];
                float s2 = 0.f;
#pragma unroll
                for (int nt4 = 0; nt4 < 4; nt4++) {
                    float d0 = acc[rt4][nt4][half * 2 + 0] - m;
                    float d1 = acc[rt4][nt4][half * 2 + 1] - m;
                    s2 += d0 * d0 + d1 * d1;
                }
                s2 += __shfl_xor_sync(0xFFFFFFFFu, s2, 1);
                s2 += __shfl_xor_sync(0xFFFFFFFFu, s2, 2);
                if (tig == 0) part[rl * 8 + wc] = s2;
            }
        }
        __syncthreads();
#pragma unroll
        for (int rt4 = 0; rt4 < 4; rt4++) {
#pragma unroll
            for (int half = 0; half < 2; half++) {
                const int rl = wr * 64 + rt4 * 16 + g + half * 8;
                const int row = blockRow + rl;
                float s2 = 0.f;
#pragma unroll
                for (int w = 0; w < 8; w++) s2 += part[rl * 8 + w];
                const float inv = rsqrtf(s2 * (1.f / 256.f) + EPS);
                const float m = mu[rt4 * 2 + half];
                float* Crow = C + (size_t)row * 256;
#pragma unroll
                for (int nt4 = 0; nt4 < 4; nt4++) {
                    const int col = wc * 32 + nt4 * 8 + tig * 2;
                    float2 out;
                    out.x = (acc[rt4][nt4][half * 2 + 0] - m) * inv * bn_g[col] + bn_b[col];
                    out.y = (acc[rt4][nt4][half * 2 + 1] - m) * inv * bn_g[col + 1] + bn_b[col + 1];
                    *(float2*)(Crow + col) = out;
                }
            }
        }
        return;
    }

#pragma unroll
    for (int rt4 = 0; rt4 < 4; rt4++) {
#pragma unroll
        for (int half = 0; half < 2; half++) {
            const int row = blockRow + wr * 64 + rt4 * 16 + g + half * 8;
            float* Crow = C + (size_t)row * Nout;
            const float* Arow = Add + (size_t)row * Nout;
#pragma unroll
            for (int nt4 = 0; nt4 < 4; nt4++) {
                const int col = blockCol + wc * 32 + nt4 * 8 + tig * 2;
                float v0 = acc[rt4][nt4][half * 2 + 0];
                float v1 = acc[rt4][nt4][half * 2 + 1];
                float2 out;
                if (mode == 0) {
                    out.x = v0 + bias[col]     + Arow[col];
                    out.y = v1 + bias[col + 1] + Arow[col + 1];
                    *(float2*)(Crow + col) = out;
                } else if (mode == 1) {
                    out.x = v0 * scale; out.y = v1 * scale;
                    *(float2*)(Crow + col) = out;
                } else if (mode == 2) {
                    out.x = v0; out.y = v1;
                    *(float2*)(Crow + col) = out;
                } else if (mode == 3) {
                    float t0 = (v0 + bias[col] - bn_mean[col]) *
                               rsqrtf(bn_var[col] + EPS) * bn_g[col] + bn_b[col];
                    float t1 = (v1 + bias[col + 1] - bn_mean[col + 1]) *
                               rsqrtf(bn_var[col + 1] + EPS) * bn_g[col + 1] + bn_b[col + 1];
                    out.x = fmaxf(t0, 0.f); out.y = fmaxf(t1, 0.f);
                    *(float2*)(Crow + col) = out;
                } else {  // mode 4: dual output q/k
                    if (col < 256) {
                        out.x = v0 * scale; out.y = v1 * scale;
                        *(float2*)(C + (size_t)row * 256 + col) = out;
                    } else {
                        out.x = v0; out.y = v1;
                        *(float2*)(C2 + (size_t)row * 256 + (col - 256)) = out;
                    }
                }
            }
        }
    }
}

// ---------------------------------------------------------------------------
// Per-chunk geometry + first MLP layers (4->256 and 6->256, relu)
// ---------------------------------------------------------------------------
__global__ __launch_bounds__(256) void geom_hidden_kernel(
    const float* __restrict__ pos,
    const float* __restrict__ w1, const float* __restrict__ b1,
    const float* __restrict__ w2, const float* __restrict__ b2,
    float* __restrict__ H1, float* __restrict__ H2, int cs)
{
    __shared__ float ps[64][3];
    __shared__ float lp[64][4];
    __shared__ float cog[3], avg[3];

    const int tid = threadIdx.x;
    const size_t gp = (size_t)blockIdx.x * cs;

    if (tid < cs) {
        ps[tid][0] = pos[(gp + tid) * 3 + 0];
        ps[tid][1] = pos[(gp + tid) * 3 + 1];
        ps[tid][2] = pos[(gp + tid) * 3 + 2];
    }
    __syncthreads();
    if (tid < 3) {
        float s = 0.f;
        for (int p = 0; p < cs; p++) s += ps[p][tid];
        cog[tid] = s / (float)cs;
    }
    __syncthreads();
    if (tid < cs) {
        float x = ps[tid][0] - cog[0];
        float y = ps[tid][1] - cog[1];
        float z = ps[tid][2] - cog[2];
        lp[tid][0] = x; lp[tid][1] = y; lp[tid][2] = z;
        lp[tid][3] = sqrtf(x * x + y * y + z * z);
    }
    __syncthreads();
    if (tid < 3) {
        float s = 0.f;
        for (int p = 0; p < cs; p++) s += lp[p][tid];
        avg[tid] = s / (float)cs;
    }
    __syncthreads();

    const int j = tid;
    float w1c[4], w2c[6];
#pragma unroll
    for (int t = 0; t < 4; t++) w1c[t] = w1[t * 256 + j];
#pragma unroll
    for (int t = 0; t < 6; t++) w2c[t] = w2[t * 256 + j];
    const float b1v = b1[j], b2v = b2[j];
    const float a0 = avg[0], a1 = avg[1], a2 = avg[2];

    for (int p = 0; p < cs; p++) {
        float x = lp[p][0], y = lp[p][1], z = lp[p][2], n = lp[p][3];
        float h1 = fmaxf(b1v + x * w1c[0] + y * w1c[1] + z * w1c[2] + n * w1c[3], 0.f);
        float h2 = fmaxf(b2v + a0 * w2c[0] + a1 * w2c[1] + a2 * w2c[2] +
                               x * w2c[3] + y * w2c[4] + z * w2c[5], 0.f);
        H1[(gp + p) * 256 + j] = f2tf32_rn(h1);
        H2[(gp + p) * 256 + j] = f2tf32_rn(h2);
    }
}

// ---------------------------------------------------------------------------
// Register-blocked chunk attention. CTA = 64 points.
// ---------------------------------------------------------------------------
#define SQ 257
#define SVP 264
#define ATTN_SMEM ((2 * 64 * SQ + 4096) * 4)

template<int CS>
__global__ __launch_bounds__(256) void attn_kernel(
    const float* __restrict__ Q, const float* __restrict__ Kf,
    const float* __restrict__ V, float* __restrict__ Out)
{
    extern __shared__ float sm[];
    float* Qs = sm;
    float* Ks = sm + 64 * SQ;
    float* P  = sm + 2 * 64 * SQ;
    float* Vs = sm;

    const int tid = threadIdx.x;
    const size_t base = (size_t)blockIdx.x * 64 * 256;

    for (int idx = tid; idx < 64 * 256; idx += 256) {
        int p = idx >> 8, t = idx & 255;
        Qs[p * SQ + t] = Q[base + idx];
        Ks[p * SQ + t] = Kf[base + idx];
    }
    __syncthreads();

    if (CS == 64) {
        const int i0 = (tid >> 4) * 4;
        const int j0 = (tid & 15) * 4;
        float acc[4][4] = {};
        for (int t = 0; t < 256; t++) {
            float qv[4], kv[4];
#pragma unroll
            for (int e = 0; e < 4; e++) qv[e] = Qs[(i0 + e) * SQ + t];
#pragma unroll
            for (int f = 0; f < 4; f++) kv[f] = Ks[(j0 + f) * SQ + t];
#pragma unroll
            for (int e = 0; e < 4; e++)
#pragma unroll
                for (int f = 0; f < 4; f++) acc[e][f] += qv[e] * kv[f];
        }
#pragma unroll
        for (int e = 0; e < 4; e++)
#pragma unroll
            for (int f = 0; f < 4; f++) P[(i0 + e) * 64 + j0 + f] = acc[e][f];
    } else {
        const int ch = tid >> 6;
        const int r  = (tid >> 2) & 15;
        const int j0 = (tid & 3) * 4;
        const int gi = ch * 16 + r;
        const int gj = ch * 16 + j0;
        float acc[4] = {};
        for (int t = 0; t < 256; t++) {
            float qv = Qs[gi * SQ + t];
#pragma unroll
            for (int f = 0; f < 4; f++) acc[f] += qv * Ks[(gj + f) * SQ + t];
        }
#pragma unroll
        for (int f = 0; f < 4; f++) P[ch * 256 + r * 16 + j0 + f] = acc[f];
    }
    __syncthreads();

    if (CS == 64) {
        const int warp = tid >> 5, lane = tid & 31;
        for (int i = warp; i < 64; i += 8) {
            float* row = P + i * 64;
            float a = row[lane], b = row[lane + 32];
            float mx = fmaxf(a, b);
#pragma unroll
            for (int o = 16; o; o >>= 1) mx = fmaxf(mx, __shfl_xor_sync(0xFFFFFFFFu, mx, o));
            float ea = __expf(a - mx), eb = __expf(b - mx);
            float sum = ea + eb;
#pragma unroll
            for (int o = 16; o; o >>= 1) sum += __shfl_xor_sync(0xFFFFFFFFu, sum, o);
            float inv = 1.f / sum;
            row[lane] = ea * inv;
            row[lane + 32] = eb * inv;
        }
    } else {
        if (tid < 64) {
            float* row = P + (tid >> 4) * 256 + (tid & 15) * 16;
            float mx = -1e30f;
#pragma unroll
            for (int j = 0; j < 16; j++) mx = fmaxf(mx, row[j]);
            float sum = 0.f;
            float e[16];
#pragma unroll
            for (int j = 0; j < 16; j++) { e[j] = __expf(row[j] - mx); sum += e[j]; }
            float inv = 1.f / sum;
#pragma unroll
            for (int j = 0; j < 16; j++) row[j] = e[j] * inv;
        }
    }
    __syncthreads();

    for (int idx = tid; idx < 64 * 256; idx += 256) {
        int p = idx >> 8, t = idx & 255;
        Vs[p * SVP + t] = V[base + idx];
    }
    __syncthreads();

    {
        const int i0 = (tid >> 4) * 4;
        const int tq = tid & 15;
        const int cb = i0 & ~(CS - 1);
        float acc[4][16] = {};
        for (int j = 0; j < CS; j++) {
            float pv[4];
            if (CS == 64) {
#pragma unroll
                for (int e = 0; e < 4; e++) pv[e] = P[(i0 + e) * 64 + j];
            } else {
                const int chk = i0 >> 4;
#pragma unroll
                for (int e = 0; e < 4; e++) pv[e] = P[chk * 256 + (i0 + e - cb) * 16 + j];
            }
            const float* vr = Vs + (cb + j) * SVP + tq;
            float vv[16];
#pragma unroll
            for (int m = 0; m < 16; m++) vv[m] = vr[m * 16];
#pragma unroll
            for (int e = 0; e < 4; e++)
#pragma unroll
                for (int m = 0; m < 16; m++) acc[e][m] += pv[e] * vv[m];
        }
#pragma unroll
        for (int e = 0; e < 4; e++)
#pragma unroll
            for (int m = 0; m < 16; m++)
                Out[base + (size_t)(i0 + e) * 256 + tq + m * 16] = f2tf32_rn(acc[e][m]);
    }
}

// ---------------------------------------------------------------------------
// kNN gather + channel max (float4), pos downsample
// ---------------------------------------------------------------------------
__global__ __launch_bounds__(128) void knn_max_kernel(
    const float* __restrict__ G, const int* __restrict__ knn,
    float* __restrict__ out)
{
    const int bm = blockIdx.x;
    const int b  = bm / MPTS;
    const int tid = threadIdx.x;
    __shared__ int idxs[KNN];
    if (tid < KNN) idxs[tid] = knn[(size_t)bm * KNN + tid];
    __syncthreads();
    float4 m = make_float4(-3.0e38f, -3.0e38f, -3.0e38f, -3.0e38f);
#pragma unroll
    for (int k = 0; k < KNN; k++) {
        const float4 gg = *(const float4*)&G[((size_t)b * NPTS + idxs[k]) * DOUT + tid * 4];
        m.x = fmaxf(m.x, gg.x); m.y = fmaxf(m.y, gg.y);
        m.z = fmaxf(m.z, gg.z); m.w = fmaxf(m.w, gg.w);
    }
    *(float4*)&out[(size_t)bm * DOUT + tid * 4] = m;
}

__global__ void posds_kernel(const float* __restrict__ pos,
                             const int* __restrict__ fps,
                             float* __restrict__ out)
{
    int p = blockIdx.x * blockDim.x + threadIdx.x;
    if (p < BATCH * MPTS) {
        int b = p / MPTS;
        int n = fps[p];
        size_t src = ((size_t)b * NPTS + n) * 3;
        out[p * 3 + 0] = pos[src + 0];
        out[p * 3 + 1] = pos[src + 1];
        out[p * 3 + 2] = pos[src + 2];
    }
}

// ---------------------------------------------------------------------------
// Orchestration
// ---------------------------------------------------------------------------
extern "C" void kernel_launch(void* const* d_in, const int* in_sizes, int n_in,
                              void* d_out, int out_size)
{
    const int s = (n_in >= 27) ? 6 : 4;

    const float* pos     = (const float*)d_in[0];
    const float* feat    = (const float*)d_in[1];
    const int*   fps     = (const int*)  d_in[2];
    const int*   knn     = (const int*)  d_in[3];
    const float* mlp1_w1 = (const float*)d_in[s + 0];
    const float* mlp1_b1 = (const float*)d_in[s + 1];
    const float* mlp1_w2 = (const float*)d_in[s + 2];
    const float* mlp1_b2 = (const float*)d_in[s + 3];
    const float* mlp2_w1 = (const float*)d_in[s + 4];
    const float* mlp2_b1 = (const float*)d_in[s + 5];
    const float* mlp2_w2 = (const float*)d_in[s + 6];
    const float* mlp2_b2 = (const float*)d_in[s + 7];
    const float* wq      = (const float*)d_in[s + 8];
    const float* wk      = (const float*)d_in[s + 9];
    const float* wv      = (const float*)d_in[s + 10];
    const float* wo      = (const float*)d_in[s + 11];
    const float* bo      = (const float*)d_in[s + 12];
    const float* ln_g    = (const float*)d_in[s + 13];
    const float* ln_b    = (const float*)d_in[s + 14];
    const float* td_w    = (const float*)d_in[s + 15];
    const float* td_b    = (const float*)d_in[s + 16];
    const float* bn_g    = (const float*)d_in[s + 17];
    const float* bn_b    = (const float*)d_in[s + 18];
    const float* bn_mean = (const float*)d_in[s + 19];
    const float* bn_var  = (const float*)d_in[s + 20];

    float *h1, *h2, *hpos, *hgeo, *qb, *kb, *vb, *sb, *fb, *g512, *wt;
    cudaGetSymbolAddress((void**)&h1,   d_h1);
    cudaGetSymbolAddress((void**)&h2,   d_h2);
    cudaGetSymbolAddress((void**)&hpos, d_hpos);
    cudaGetSymbolAddress((void**)&hgeo, d_hgeo);
    cudaGetSymbolAddress((void**)&qb,   d_q);
    cudaGetSymbolAddress((void**)&kb,   d_k);
    cudaGetSymbolAddress((void**)&vb,   d_v);
    cudaGetSymbolAddress((void**)&sb,   d_s);
    cudaGetSymbolAddress((void**)&fb,   d_f);
    cudaGetSymbolAddress((void**)&g512, d_g512);
    cudaGetSymbolAddress((void**)&wt,   d_wt);

    cudaFuncSetAttribute(tc_gemm,
                         cudaFuncAttributeMaxDynamicSharedMemorySize, TC_SMEM_TOTAL);
    cudaFuncSetAttribute(attn_kernel<16>,
                         cudaFuncAttributeMaxDynamicSharedMemorySize, ATTN_SMEM);
    cudaFuncSetAttribute(attn_kernel<64>,
                         cudaFuncAttributeMaxDynamicSharedMemorySize, ATTN_SMEM);

    transpose_all<<<dim3(8, 8, 14), 256>>>(mlp1_w2, mlp2_w2, wq, wk, wv, wo, td_w, wt);

    const dim3 gemmBlk(512);
    const dim3 grid256(1, RTOT / 128);   // Nout=256: 512 CTAs
    const dim3 grid512(2, RTOT / 128);   // Nout=512: 1024 CTAs

    for (int blk = 0; blk < 2; blk++) {
        const int cs = (blk == 0) ? 16 : 64;
        const int i  = blk;
        const float* fin = (blk == 0) ? feat : fb;
        const size_t bOff = (size_t)i * 256;
        float* Wt0 = wt + (size_t)(i * 6) * SLOT;

        geom_hidden_kernel<<<RTOT / cs, 256>>>(
            pos, mlp1_w1 + (size_t)i * 4 * 256, mlp1_b1 + bOff,
            mlp2_w1 + (size_t)i * 6 * 256, mlp2_b1 + bOff, h1, h2, cs);

        tc_gemm<<<grid256, gemmBlk, TC_SMEM_TOTAL>>>(h1, Wt0 + 0 * SLOT, mlp1_b2 + bOff, fin,
            hpos, nullptr, DIM, 0, 1.f, nullptr, nullptr, nullptr, nullptr);
        tc_gemm<<<grid256, gemmBlk, TC_SMEM_TOTAL>>>(h2, Wt0 + 1 * SLOT, mlp2_b2 + bOff, fin,
            hgeo, nullptr, DIM, 0, 1.f, nullptr, nullptr, nullptr, nullptr);
        tc_gemm<<<grid512, gemmBlk, TC_SMEM_TOTAL>>>(hgeo, Wt0 + 2 * SLOT, nullptr, feat,
            qb, kb, DOUT, 4, 1.f / 16.f, nullptr, nullptr, nullptr, nullptr);
        tc_gemm<<<grid256, gemmBlk, TC_SMEM_TOTAL>>>(hpos, Wt0 + 4 * SLOT, nullptr, feat,
            vb, nullptr, DIM, 2, 1.f, nullptr, nullptr, nullptr, nullptr);

        if (cs == 16)
            attn_kernel<16><<<RTOT / 64, 256, ATTN_SMEM>>>(qb, kb, vb, sb);
        else
            attn_kernel<64><<<RTOT / 64, 256, ATTN_SMEM>>>(qb, kb, vb, sb);

        // fused: fb = LN(hpos + attn@wo + bo)
        tc_gemm<<<grid256, gemmBlk, TC_SMEM_TOTAL>>>(sb, Wt0 + 5 * SLOT, bo + bOff, hpos,
            fb, nullptr, DIM, 5, 1.f, ln_g + bOff, ln_b + bOff, nullptr, nullptr);
    }

    tc_gemm<<<grid512, gemmBlk, TC_SMEM_TOTAL>>>(fb, wt + 12 * SLOT, td_b, feat,
        g512, nullptr, DOUT, 3, 1.f, bn_g, bn_b, bn_mean, bn_var);

    float* outp = (float*)d_out;
    posds_kernel<<<(BATCH * MPTS + 255) / 256, 256>>>(pos, fps, outp);
    knn_max_kernel<<<BATCH * MPTS, 128>>>(g512, knn, outp + BATCH * MPTS * 3);
}

// round 10
// speedup vs baseline: 1.0781x; 1.0781x over previous
#include <cuda_runtime.h>
#include <cuda_bf16.h>
#include <math.h>
#include <stdint.h>

// Problem constants
#define BATCH 8
#define NPTS  8192
#define DIM   256
#define DOUT  512
#define MPTS  2048
#define KNN   16
#define RTOT  (BATCH * NPTS)   // 65536 rows
#define EPS   1e-5f

// ---------------------------------------------------------------------------
// Scratch
// ---------------------------------------------------------------------------
__device__ __align__(128) float d_h1  [(size_t)RTOT * DIM];
__device__ __align__(128) float d_h2  [(size_t)RTOT * DIM];
__device__ __align__(128) float d_hpos[(size_t)RTOT * DIM];
__device__ __align__(128) float d_hgeo[(size_t)RTOT * DIM];
__device__ __align__(128) float d_q   [(size_t)RTOT * DIM];
__device__ __align__(128) float d_k   [(size_t)RTOT * DIM];
__device__ __align__(128) float d_v   [(size_t)RTOT * DIM];
__device__ __align__(128) float d_s   [(size_t)RTOT * DIM];
__device__ __align__(128) float d_f   [(size_t)RTOT * DIM];
__device__ __align__(128) float d_g512[(size_t)RTOT * DOUT];
__device__ __align__(128) float d_wt  [14 * 256 * 256];

#define SLOT (256 * 256)

// ---------------------------------------------------------------------------
// helpers
// ---------------------------------------------------------------------------
__device__ __forceinline__ float f2tf32_rn(float v) {
    uint32_t u;
    asm("cvt.rna.tf32.f32 %0, %1;" : "=r"(u) : "f"(v));
    return __uint_as_float(u);
}

__device__ __forceinline__ void mma_tf32(float* c, const uint32_t* a, const uint32_t* b) {
    asm volatile(
        "mma.sync.aligned.m16n8k8.row.col.f32.tf32.tf32.f32 "
        "{%0,%1,%2,%3}, {%4,%5,%6,%7}, {%8,%9}, {%0,%1,%2,%3};"
        : "+f"(c[0]), "+f"(c[1]), "+f"(c[2]), "+f"(c[3])
        : "r"(a[0]), "r"(a[1]), "r"(a[2]), "r"(a[3]), "r"(b[0]), "r"(b[1]));
}

__device__ __forceinline__ uint32_t smem_u32(const void* p) {
    uint32_t a;
    asm("{ .reg .u64 t; cvta.to.shared.u64 t, %1; cvt.u32.u64 %0, t; }" : "=r"(a) : "l"(p));
    return a;
}

#define CP_ASYNC16(dst, src) \
    asm volatile("cp.async.cg.shared.global [%0], [%1], 16;" :: "r"(dst), "l"(src))
#define CP_COMMIT() asm volatile("cp.async.commit_group;")
template<int N> __device__ __forceinline__ void cp_wait() {
    asm volatile("cp.async.wait_group %0;" :: "n"(N));
}

#define LDSM_X4(r, addr) \
    asm volatile("ldmatrix.sync.aligned.m8n8.x4.shared.b16 {%0,%1,%2,%3}, [%4];" \
        : "=r"((r)[0]), "=r"((r)[1]), "=r"((r)[2]), "=r"((r)[3]) : "r"(addr))
#define LDSM_X2(r, addr) \
    asm volatile("ldmatrix.sync.aligned.m8n8.x2.shared.b16 {%0,%1}, [%2];" \
        : "=r"((r)[0]), "=r"((r)[1]) : "r"(addr))

// ---------------------------------------------------------------------------
// Batched weight transpose (rounded to tf32-rn at write)
// ---------------------------------------------------------------------------
__global__ __launch_bounds__(256) void transpose_all(
    const float* __restrict__ m1w2, const float* __restrict__ m2w2,
    const float* __restrict__ wq, const float* __restrict__ wk,
    const float* __restrict__ wv, const float* __restrict__ wo,
    const float* __restrict__ td, float* __restrict__ wt)
{
    __shared__ float t[32][33];
    const int z = blockIdx.z;
    const float* src;
    int srcN = 256, colOff = 0;
    float* dst;
    if (z < 12) {
        const int i = z / 6, j = z % 6;
        const size_t off = (size_t)i * SLOT;
        switch (j) {
            case 0: src = m1w2 + off; break;
            case 1: src = m2w2 + off; break;
            case 2: src = wq   + off; break;
            case 3: src = wk   + off; break;
            case 4: src = wv   + off; break;
            default: src = wo  + off; break;
        }
        dst = wt + (size_t)(i * 6 + j) * SLOT;
    } else {
        src = td; srcN = 512; colOff = (z - 12) * 256;
        dst = wt + (size_t)(12 + (z - 12)) * SLOT;
    }

    const int bx = blockIdx.x * 32;
    const int by = blockIdx.y * 32;
    const int tx = threadIdx.x & 31, ty = threadIdx.x >> 5;
#pragma unroll
    for (int i = ty; i < 32; i += 8)
        t[i][tx] = src[(size_t)(by + i) * srcN + colOff + bx + tx];
    __syncthreads();
#pragma unroll
    for (int i = ty; i < 32; i += 8)
        dst[(size_t)(bx + i) * 256 + by + tx] = f2tf32_rn(t[tx][i]);
}

// ---------------------------------------------------------------------------
// tf32 mma.sync GEMM (R8 config), cp.async + ldmatrix.
// CTA tile 128x128, 256 threads (8 warps, 2x4), warp tile 64x32.
// K chunks of 32 floats, 3-stage ring (32KB/stage), 2 CTAs/SM.
// blockIdx.z==1 switches to job 2 (A2/W2/bias2/Cb) with the same mode.
// modes: 0 = +bias[c]+Add[r,c]  1 = *scale  2 = none  3 = relu(bn(acc+bias))
//        4 = dual output: col<256 -> C (q, *scale), col>=256 -> C2 (k)
// ---------------------------------------------------------------------------
#define STG_BYTES 32768                 // A 16KB + B 16KB
#define TC_SMEM_TOTAL (3 * STG_BYTES)   // 96KB

__global__ void __launch_bounds__(256, 2) tc_gemm(
    const float* __restrict__ A, const float* __restrict__ Wt,
    const float* __restrict__ bias, const float* __restrict__ Add,
    float* __restrict__ C, float* __restrict__ C2,
    int Nout, int mode, float scale,
    const float* __restrict__ bn_g, const float* __restrict__ bn_b,
    const float* __restrict__ bn_mean, const float* __restrict__ bn_var,
    const float* __restrict__ A2, const float* __restrict__ W2,
    const float* __restrict__ bias2, float* __restrict__ Cb)
{
    extern __shared__ char smem[];
    const uint32_t sbase = smem_u32(smem);
    const int tid  = threadIdx.x;
    const int lane = tid & 31;
    const int wid  = tid >> 5;
    const int wr   = wid >> 2;       // 0..1 -> 64-row slab
    const int wc   = wid & 3;        // 0..3 -> 32-col slab

    if (blockIdx.z == 1) {           // second batched job
        A = A2; Wt = W2; bias = bias2; C = Cb;
    }

    const int blockRow = blockIdx.y * 128;
    const int blockCol = blockIdx.x * 128;

    const float* Abase = A  + (size_t)blockRow * 256;
    const float* Bbase = Wt + (size_t)blockCol * 256;

    // ---- cp.async loader: 4 16B per thread for A, 4 for B per chunk ----
    int rowL[4], qL[4];
    uint32_t offL[4];
#pragma unroll
    for (int i = 0; i < 4; i++) {
        const int idx = tid + i * 256;
        rowL[i] = idx >> 3;                 // 0..127
        qL[i]   = idx & 7;                  // 16B unit within row
        offL[i] = (uint32_t)rowL[i] * 128u + (uint32_t)((qL[i] ^ (rowL[i] & 7)) * 16);
    }

    auto issue_chunk = [&](int c, int s) {
        const int k0 = c * 32;
        const uint32_t ab = sbase + (uint32_t)s * STG_BYTES;
        const uint32_t bb = ab + 16384u;
#pragma unroll
        for (int i = 0; i < 4; i++)
            CP_ASYNC16(ab + offL[i], Abase + (size_t)rowL[i] * 256 + k0 + qL[i] * 4);
#pragma unroll
        for (int i = 0; i < 4; i++)
            CP_ASYNC16(bb + offL[i], Bbase + (size_t)rowL[i] * 256 + k0 + qL[i] * 4);
        CP_COMMIT();
    };

    // ---- ldmatrix addressing ----
    const int l7  = lane & 7;
    const int hA  = lane >> 4;
    const int hB  = (lane >> 3) & 1;
    uint32_t aOff[4], bOff[4];
#pragma unroll
    for (int t = 0; t < 4; t++) {
        const int rA = wr * 64 + t * 16 + ((lane >> 3) & 1) * 8 + l7;
        aOff[t] = (uint32_t)rA * 128u;
        const int rB = wc * 32 + t * 8 + l7;
        bOff[t] = (uint32_t)rB * 128u;
    }

    float acc[4][4][4];
#pragma unroll
    for (int i = 0; i < 4; i++)
#pragma unroll
        for (int j = 0; j < 4; j++)
#pragma unroll
            for (int e = 0; e < 4; e++) acc[i][j][e] = 0.f;

    auto compute = [&](int s) {
        const uint32_t sA = sbase + (uint32_t)s * STG_BYTES;
        const uint32_t sB = sA + 16384u;
#pragma unroll
        for (int kt = 0; kt < 4; kt++) {
            const uint32_t qa = (uint32_t)((((kt << 1) + hA) ^ l7) << 4);
            const uint32_t qb = (uint32_t)((((kt << 1) + hB) ^ l7) << 4);
            uint32_t aF[4][4], bF[4][2];
#pragma unroll
            for (int rt4 = 0; rt4 < 4; rt4++)
                LDSM_X4(aF[rt4], sA + aOff[rt4] + qa);
#pragma unroll
            for (int nt4 = 0; nt4 < 4; nt4++)
                LDSM_X2(bF[nt4], sB + bOff[nt4] + qb);
#pragma unroll
            for (int rt4 = 0; rt4 < 4; rt4++)
#pragma unroll
                for (int nt4 = 0; nt4 < 4; nt4++)
                    mma_tf32(acc[rt4][nt4], aF[rt4], bF[nt4]);
        }
    };

    issue_chunk(0, 0);
    issue_chunk(1, 1);
#pragma unroll
    for (int c = 0; c < 8; c++) {
        if (c == 7) cp_wait<0>(); else cp_wait<1>();
        __syncthreads();
        if (c + 2 < 8) issue_chunk(c + 2, (c + 2) % 3);
        compute(c % 3);
    }

    // epilogue
    const int g   = lane >> 2;
    const int tig = lane & 3;
#pragma unroll
    for (int rt4 = 0; rt4 < 4; rt4++) {
#pragma unroll
        for (int half = 0; half < 2; half++) {
            const int row = blockRow + wr * 64 + rt4 * 16 + g + half * 8;
            float* Crow = C + (size_t)row * Nout;
            const float* Arow = Add + (size_t)row * Nout;
#pragma unroll
            for (int nt4 = 0; nt4 < 4; nt4++) {
                const int col = blockCol + wc * 32 + nt4 * 8 + tig * 2;
                float v0 = acc[rt4][nt4][half * 2 + 0];
                float v1 = acc[rt4][nt4][half * 2 + 1];
                float2 out;
                if (mode == 0) {
                    out.x = v0 + bias[col]     + Arow[col];
                    out.y = v1 + bias[col + 1] + Arow[col + 1];
                    *(float2*)(Crow + col) = out;
                } else if (mode == 1) {
                    out.x = v0 * scale; out.y = v1 * scale;
                    *(float2*)(Crow + col) = out;
                } else if (mode == 2) {
                    out.x = v0; out.y = v1;
                    *(float2*)(Crow + col) = out;
                } else if (mode == 3) {
                    float t0 = (v0 + bias[col] - bn_mean[col]) *
                               rsqrtf(bn_var[col] + EPS) * bn_g[col] + bn_b[col];
                    float t1 = (v1 + bias[col + 1] - bn_mean[col + 1]) *
                               rsqrtf(bn_var[col + 1] + EPS) * bn_g[col + 1] + bn_b[col + 1];
                    out.x = fmaxf(t0, 0.f); out.y = fmaxf(t1, 0.f);
                    *(float2*)(Crow + col) = out;
                } else {  // mode 4: dual output q/k
                    if (col < 256) {
                        out.x = v0 * scale; out.y = v1 * scale;
                        *(float2*)(C + (size_t)row * 256 + col) = out;
                    } else {
                        out.x = v0; out.y = v1;
                        *(float2*)(C2 + (size_t)row * 256 + (col - 256)) = out;
                    }
                }
            }
        }
    }
}

// ---------------------------------------------------------------------------
// Fused wo-GEMM + LayerNorm: C = LN(Add + A@Wt^T + bias) * g + b
// CTA tile 64x256 (full feature row in one CTA), 256 threads (8 warps, 2x4),
// warp tile 32x64. 3-stage ring, stage = A 8KB + B 32KB = 40KB -> 120KB smem.
// ---------------------------------------------------------------------------
#define LN_STG_BYTES 40960
#define LN_SMEM_TOTAL (3 * LN_STG_BYTES)   // 122880

__global__ void __launch_bounds__(256, 1) tc_gemm_ln(
    const float* __restrict__ A, const float* __restrict__ Wt,
    const float* __restrict__ bias, const float* __restrict__ Add,
    float* __restrict__ C,
    const float* __restrict__ lng, const float* __restrict__ lnb)
{
    extern __shared__ char smem[];
    const uint32_t sbase = smem_u32(smem);
    const int tid  = threadIdx.x;
    const int lane = tid & 31;
    const int wid  = tid >> 5;
    const int wr   = wid >> 2;       // 0..1 -> 32-row slab
    const int wc   = wid & 3;        // 0..3 -> 64-col slab

    const int blockRow = blockIdx.y * 64;
    const float* Abase = A + (size_t)blockRow * 256;

    // loaders: A 512 f4/chunk -> 2/thread; B 2048 f4/chunk -> 8/thread
    int rowLA[2], qLA[2]; uint32_t offLA[2];
#pragma unroll
    for (int i = 0; i < 2; i++) {
        const int idx = tid + i * 256;
        rowLA[i] = idx >> 3; qLA[i] = idx & 7;
        offLA[i] = (uint32_t)rowLA[i] * 128u + (uint32_t)((qLA[i] ^ (rowLA[i] & 7)) * 16);
    }
    int rowLB[8], qLB[8]; uint32_t offLB[8];
#pragma unroll
    for (int i = 0; i < 8; i++) {
        const int idx = tid + i * 256;
        rowLB[i] = idx >> 3; qLB[i] = idx & 7;
        offLB[i] = (uint32_t)rowLB[i] * 128u + (uint32_t)((qLB[i] ^ (rowLB[i] & 7)) * 16);
    }

    auto issue_chunk = [&](int c, int s) {
        const int k0 = c * 32;
        const uint32_t ab = sbase + (uint32_t)s * LN_STG_BYTES;
        const uint32_t bb = ab + 8192u;
#pragma unroll
        for (int i = 0; i < 2; i++)
            CP_ASYNC16(ab + offLA[i], Abase + (size_t)rowLA[i] * 256 + k0 + qLA[i] * 4);
#pragma unroll
        for (int i = 0; i < 8; i++)
            CP_ASYNC16(bb + offLB[i], Wt + (size_t)rowLB[i] * 256 + k0 + qLB[i] * 4);
        CP_COMMIT();
    };

    const int l7 = lane & 7;
    const int hA = lane >> 4;
    const int hB = (lane >> 3) & 1;
    uint32_t aOff[2], bOff[8];
#pragma unroll
    for (int t = 0; t < 2; t++) {
        const int rA = wr * 32 + t * 16 + ((lane >> 3) & 1) * 8 + l7;
        aOff[t] = (uint32_t)rA * 128u;
    }
#pragma unroll
    for (int n = 0; n < 8; n++) {
        const int rB = wc * 64 + n * 8 + l7;
        bOff[n] = (uint32_t)rB * 128u;
    }

    float acc[2][8][4];
#pragma unroll
    for (int i = 0; i < 2; i++)
#pragma unroll
        for (int j = 0; j < 8; j++)
#pragma unroll
            for (int e = 0; e < 4; e++) acc[i][j][e] = 0.f;

    auto compute = [&](int s) {
        const uint32_t sA = sbase + (uint32_t)s * LN_STG_BYTES;
        const uint32_t sB = sA + 8192u;
#pragma unroll
        for (int kt = 0; kt < 4; kt++) {
            const uint32_t qa = (uint32_t)((((kt << 1) + hA) ^ l7) << 4);
            const uint32_t qb = (uint32_t)((((kt << 1) + hB) ^ l7) << 4);
            uint32_t aF[2][4], bF[8][2];
#pragma unroll
            for (int t = 0; t < 2; t++)
                LDSM_X4(aF[t], sA + aOff[t] + qa);
#pragma unroll
            for (int n = 0; n < 8; n++)
                LDSM_X2(bF[n], sB + bOff[n] + qb);
#pragma unroll
            for (int t = 0; t < 2; t++)
#pragma unroll
                for (int n = 0; n < 8; n++)
                    mma_tf32(acc[t][n], aF[t], bF[n]);
        }
    };

    issue_chunk(0, 0);
    issue_chunk(1, 1);
#pragma unroll
    for (int c = 0; c < 8; c++) {
        if (c == 7) cp_wait<0>(); else cp_wait<1>();
        __syncthreads();
        if (c + 2 < 8) issue_chunk(c + 2, (c + 2) % 3);
        compute(c % 3);
    }

    // ---- LN epilogue ----
    const int g   = lane >> 2;
    const int tig = lane & 3;
    float* part = (float*)smem;   // [64][4] partials (stage-0 region, drained)
    float mu[4];

    // pass 0: v = acc + bias + Add; per-row partial sums
#pragma unroll
    for (int t = 0; t < 2; t++) {
#pragma unroll
        for (int half = 0; half < 2; half++) {
            const int rl  = wr * 32 + t * 16 + g + half * 8;
            const int row = blockRow + rl;
            const float* Arow = Add + (size_t)row * 256;
            float s = 0.f;
#pragma unroll
            for (int n = 0; n < 8; n++) {
                const int col = wc * 64 + n * 8 + tig * 2;
                float v0 = acc[t][n][half * 2 + 0] + bias[col]     + Arow[col];
                float v1 = acc[t][n][half * 2 + 1] + bias[col + 1] + Arow[col + 1];
                acc[t][n][half * 2 + 0] = v0;
                acc[t][n][half * 2 + 1] = v1;
                s += v0 + v1;
            }
            s += __shfl_xor_sync(0xFFFFFFFFu, s, 1);
            s += __shfl_xor_sync(0xFFFFFFFFu, s, 2);
            if (tig == 0) part[rl * 4 + wc] = s;
        }
    }
    __syncthreads();
#pragma unroll
    for (int t = 0; t < 2; t++)
#pragma unroll
        for (int half = 0; half < 2; half++) {
            const int rl = wr * 32 + t * 16 + g + half * 8;
            mu[t * 2 + half] = (part[rl * 4 + 0] + part[rl * 4 + 1] +
                                part[rl * 4 + 2] + part[rl * 4 + 3]) * (1.f / 256.f);
        }
    __syncthreads();
    // pass 1: centered variance
#pragma unroll
    for (int t = 0; t < 2; t++) {
#pragma unroll
        for (int half = 0; half < 2; half++) {
            const int rl = wr * 32 + t * 16 + g + half * 8;
            const float m = mu[t * 2 + half];
            float s2 = 0.f;
#pragma unroll
            for (int n = 0; n < 8; n++) {
                float d0 = acc[t][n][half * 2 + 0] - m;
                float d1 = acc[t][n][half * 2 + 1] - m;
                s2 += d0 * d0 + d1 * d1;
            }
            s2 += __shfl_xor_sync(0xFFFFFFFFu, s2, 1);
            s2 += __shfl_xor_sync(0xFFFFFFFFu, s2, 2);
            if (tig == 0) part[rl * 4 + wc] = s2;
        }
    }
    __syncthreads();
#pragma unroll
    for (int t = 0; t < 2; t++) {
#pragma unroll
        for (int half = 0; half < 2; half++) {
            const int rl  = wr * 32 + t * 16 + g + half * 8;
            const int row = blockRow + rl;
            const float s2 = part[rl * 4 + 0] + part[rl * 4 + 1] +
                             part[rl * 4 + 2] + part[rl * 4 + 3];
            const float inv = rsqrtf(s2 * (1.f / 256.f) + EPS);
            const float m = mu[t * 2 + half];
            float* Crow = C + (size_t)row * 256;
#pragma unroll
            for (int n = 0; n < 8; n++) {
                const int col = wc * 64 + n * 8 + tig * 2;
                float2 out;
                out.x = (acc[t][n][half * 2 + 0] - m) * inv * lng[col]     + lnb[col];
                out.y = (acc[t][n][half * 2 + 1] - m) * inv * lng[col + 1] + lnb[col + 1];
                *(float2*)(Crow + col) = out;
            }
        }
    }
}

// ---------------------------------------------------------------------------
// Per-chunk geometry + first MLP layers (4->256 and 6->256, relu)
// ---------------------------------------------------------------------------
__global__ __launch_bounds__(256) void geom_hidden_kernel(
    const float* __restrict__ pos,
    const float* __restrict__ w1, const float* __restrict__ b1,
    const float* __restrict__ w2, const float* __restrict__ b2,
    float* __restrict__ H1, float* __restrict__ H2, int cs)
{
    __shared__ float ps[64][3];
    __shared__ float lp[64][4];
    __shared__ float cog[3], avg[3];

    const int tid = threadIdx.x;
    const size_t gp = (size_t)blockIdx.x * cs;

    if (tid < cs) {
        ps[tid][0] = pos[(gp + tid) * 3 + 0];
        ps[tid][1] = pos[(gp + tid) * 3 + 1];
        ps[tid][2] = pos[(gp + tid) * 3 + 2];
    }
    __syncthreads();
    if (tid < 3) {
        float s = 0.f;
        for (int p = 0; p < cs; p++) s += ps[p][tid];
        cog[tid] = s / (float)cs;
    }
    __syncthreads();
    if (tid < cs) {
        float x = ps[tid][0] - cog[0];
        float y = ps[tid][1] - cog[1];
        float z = ps[tid][2] - cog[2];
        lp[tid][0] = x; lp[tid][1] = y; lp[tid][2] = z;
        lp[tid][3] = sqrtf(x * x + y * y + z * z);
    }
    __syncthreads();
    if (tid < 3) {
        float s = 0.f;
        for (int p = 0; p < cs; p++) s += lp[p][tid];
        avg[tid] = s / (float)cs;
    }
    __syncthreads();

    const int j = tid;
    float w1c[4], w2c[6];
#pragma unroll
    for (int t = 0; t < 4; t++) w1c[t] = w1[t * 256 + j];
#pragma unroll
    for (int t = 0; t < 6; t++) w2c[t] = w2[t * 256 + j];
    const float b1v = b1[j], b2v = b2[j];
    const float a0 = avg[0], a1 = avg[1], a2 = avg[2];

    for (int p = 0; p < cs; p++) {
        float x = lp[p][0], y = lp[p][1], z = lp[p][2], n = lp[p][3];
        float h1 = fmaxf(b1v + x * w1c[0] + y * w1c[1] + z * w1c[2] + n * w1c[3], 0.f);
        float h2 = fmaxf(b2v + a0 * w2c[0] + a1 * w2c[1] + a2 * w2c[2] +
                               x * w2c[3] + y * w2c[4] + z * w2c[5], 0.f);
        H1[(gp + p) * 256 + j] = f2tf32_rn(h1);
        H2[(gp + p) * 256 + j] = f2tf32_rn(h2);
    }
}

// ---------------------------------------------------------------------------
// Register-blocked chunk attention. CTA = 64 points.
// ---------------------------------------------------------------------------
#define SQ 257
#define SVP 264
#define ATTN_SMEM ((2 * 64 * SQ + 4096) * 4)

template<int CS>
__global__ __launch_bounds__(256) void attn_kernel(
    const float* __restrict__ Q, const float* __restrict__ Kf,
    const float* __restrict__ V, float* __restrict__ Out)
{
    extern __shared__ float sm[];
    float* Qs = sm;
    float* Ks = sm + 64 * SQ;
    float* P  = sm + 2 * 64 * SQ;
    float* Vs = sm;

    const int tid = threadIdx.x;
    const size_t base = (size_t)blockIdx.x * 64 * 256;

    for (int idx = tid; idx < 64 * 256; idx += 256) {
        int p = idx >> 8, t = idx & 255;
        Qs[p * SQ + t] = Q[base + idx];
        Ks[p * SQ + t] = Kf[base + idx];
    }
    __syncthreads();

    if (CS == 64) {
        const int i0 = (tid >> 4) * 4;
        const int j0 = (tid & 15) * 4;
        float acc[4][4] = {};
        for (int t = 0; t < 256; t++) {
            float qv[4], kv[4];
#pragma unroll
            for (int e = 0; e < 4; e++) qv[e] = Qs[(i0 + e) * SQ + t];
#pragma unroll
            for (int f = 0; f < 4; f++) kv[f] = Ks[(j0 + f) * SQ + t];
#pragma unroll
            for (int e = 0; e < 4; e++)
#pragma unroll
                for (int f = 0; f < 4; f++) acc[e][f] += qv[e] * kv[f];
        }
#pragma unroll
        for (int e = 0; e < 4; e++)
#pragma unroll
            for (int f = 0; f < 4; f++) P[(i0 + e) * 64 + j0 + f] = acc[e][f];
    } else {
        const int ch = tid >> 6;
        const int r  = (tid >> 2) & 15;
        const int j0 = (tid & 3) * 4;
        const int gi = ch * 16 + r;
        const int gj = ch * 16 + j0;
        float acc[4] = {};
        for (int t = 0; t < 256; t++) {
            float qv = Qs[gi * SQ + t];
#pragma unroll
            for (int f = 0; f < 4; f++) acc[f] += qv * Ks[(gj + f) * SQ + t];
        }
#pragma unroll
        for (int f = 0; f < 4; f++) P[ch * 256 + r * 16 + j0 + f] = acc[f];
    }
    __syncthreads();

    if (CS == 64) {
        const int warp = tid >> 5, lane = tid & 31;
        for (int i = warp; i < 64; i += 8) {
            float* row = P + i * 64;
            float a = row[lane], b = row[lane + 32];
            float mx = fmaxf(a, b);
#pragma unroll
            for (int o = 16; o; o >>= 1) mx = fmaxf(mx, __shfl_xor_sync(0xFFFFFFFFu, mx, o));
            float ea = __expf(a - mx), eb = __expf(b - mx);
            float sum = ea + eb;
#pragma unroll
            for (int o = 16; o; o >>= 1) sum += __shfl_xor_sync(0xFFFFFFFFu, sum, o);
            float inv = 1.f / sum;
            row[lane] = ea * inv;
            row[lane + 32] = eb * inv;
        }
    } else {
        if (tid < 64) {
            float* row = P + (tid >> 4) * 256 + (tid & 15) * 16;
            float mx = -1e30f;
#pragma unroll
            for (int j = 0; j < 16; j++) mx = fmaxf(mx, row[j]);
            float sum = 0.f;
            float e[16];
#pragma unroll
            for (int j = 0; j < 16; j++) { e[j] = __expf(row[j] - mx); sum += e[j]; }
            float inv = 1.f / sum;
#pragma unroll
            for (int j = 0; j < 16; j++) row[j] = e[j] * inv;
        }
    }
    __syncthreads();

    for (int idx = tid; idx < 64 * 256; idx += 256) {
        int p = idx >> 8, t = idx & 255;
        Vs[p * SVP + t] = V[base + idx];
    }
    __syncthreads();

    {
        const int i0 = (tid >> 4) * 4;
        const int tq = tid & 15;
        const int cb = i0 & ~(CS - 1);
        float acc[4][16] = {};
        for (int j = 0; j < CS; j++) {
            float pv[4];
            if (CS == 64) {
#pragma unroll
                for (int e = 0; e < 4; e++) pv[e] = P[(i0 + e) * 64 + j];
            } else {
                const int chk = i0 >> 4;
#pragma unroll
                for (int e = 0; e < 4; e++) pv[e] = P[chk * 256 + (i0 + e - cb) * 16 + j];
            }
            const float* vr = Vs + (cb + j) * SVP + tq;
            float vv[16];
#pragma unroll
            for (int m = 0; m < 16; m++) vv[m] = vr[m * 16];
#pragma unroll
            for (int e = 0; e < 4; e++)
#pragma unroll
                for (int m = 0; m < 16; m++) acc[e][m] += pv[e] * vv[m];
        }
#pragma unroll
        for (int e = 0; e < 4; e++)
#pragma unroll
            for (int m = 0; m < 16; m++)
                Out[base + (size_t)(i0 + e) * 256 + tq + m * 16] = f2tf32_rn(acc[e][m]);
    }
}

// ---------------------------------------------------------------------------
// kNN gather + channel max (float4) + fused pos downsample
// ---------------------------------------------------------------------------
__global__ __launch_bounds__(128) void knn_max_kernel(
    const float* __restrict__ G, const int* __restrict__ knn,
    const float* __restrict__ pos, const int* __restrict__ fps,
    float* __restrict__ outPos, float* __restrict__ outFeat)
{
    const int bm = blockIdx.x;
    const int b  = bm / MPTS;
    const int tid = threadIdx.x;
    __shared__ int idxs[KNN];
    if (tid < KNN) idxs[tid] = knn[(size_t)bm * KNN + tid];
    if (tid >= 32 && tid < 35) {
        const int c = tid - 32;
        outPos[bm * 3 + c] = pos[((size_t)b * NPTS + fps[bm]) * 3 + c];
    }
    __syncthreads();
    float4 m = make_float4(-3.0e38f, -3.0e38f, -3.0e38f, -3.0e38f);
#pragma unroll
    for (int k = 0; k < KNN; k++) {
        const float4 gg = *(const float4*)&G[((size_t)b * NPTS + idxs[k]) * DOUT + tid * 4];
        m.x = fmaxf(m.x, gg.x); m.y = fmaxf(m.y, gg.y);
        m.z = fmaxf(m.z, gg.z); m.w = fmaxf(m.w, gg.w);
    }
    *(float4*)&outFeat[(size_t)bm * DOUT + tid * 4] = m;
}

// ---------------------------------------------------------------------------
// Orchestration
// ---------------------------------------------------------------------------
extern "C" void kernel_launch(void* const* d_in, const int* in_sizes, int n_in,
                              void* d_out, int out_size)
{
    const int s = (n_in >= 27) ? 6 : 4;

    const float* pos     = (const float*)d_in[0];
    const float* feat    = (const float*)d_in[1];
    const int*   fps     = (const int*)  d_in[2];
    const int*   knn     = (const int*)  d_in[3];
    const float* mlp1_w1 = (const float*)d_in[s + 0];
    const float* mlp1_b1 = (const float*)d_in[s + 1];
    const float* mlp1_w2 = (const float*)d_in[s + 2];
    const float* mlp1_b2 = (const float*)d_in[s + 3];
    const float* mlp2_w1 = (const float*)d_in[s + 4];
    const float* mlp2_b1 = (const float*)d_in[s + 5];
    const float* mlp2_w2 = (const float*)d_in[s + 6];
    const float* mlp2_b2 = (const float*)d_in[s + 7];
    const float* wq      = (const float*)d_in[s + 8];
    const float* wk      = (const float*)d_in[s + 9];
    const float* wv      = (const float*)d_in[s + 10];
    const float* wo      = (const float*)d_in[s + 11];
    const float* bo      = (const float*)d_in[s + 12];
    const float* ln_g    = (const float*)d_in[s + 13];
    const float* ln_b    = (const float*)d_in[s + 14];
    const float* td_w    = (const float*)d_in[s + 15];
    const float* td_b    = (const float*)d_in[s + 16];
    const float* bn_g    = (const float*)d_in[s + 17];
    const float* bn_b    = (const float*)d_in[s + 18];
    const float* bn_mean = (const float*)d_in[s + 19];
    const float* bn_var  = (const float*)d_in[s + 20];

    float *h1, *h2, *hpos, *hgeo, *qb, *kb, *vb, *sb, *fb, *g512, *wt;
    cudaGetSymbolAddress((void**)&h1,   d_h1);
    cudaGetSymbolAddress((void**)&h2,   d_h2);
    cudaGetSymbolAddress((void**)&hpos, d_hpos);
    cudaGetSymbolAddress((void**)&hgeo, d_hgeo);
    cudaGetSymbolAddress((void**)&qb,   d_q);
    cudaGetSymbolAddress((void**)&kb,   d_k);
    cudaGetSymbolAddress((void**)&vb,   d_v);
    cudaGetSymbolAddress((void**)&sb,   d_s);
    cudaGetSymbolAddress((void**)&fb,   d_f);
    cudaGetSymbolAddress((void**)&g512, d_g512);
    cudaGetSymbolAddress((void**)&wt,   d_wt);

    cudaFuncSetAttribute(tc_gemm,
                         cudaFuncAttributeMaxDynamicSharedMemorySize, TC_SMEM_TOTAL);
    cudaFuncSetAttribute(tc_gemm_ln,
                         cudaFuncAttributeMaxDynamicSharedMemorySize, LN_SMEM_TOTAL);
    cudaFuncSetAttribute(attn_kernel<16>,
                         cudaFuncAttributeMaxDynamicSharedMemorySize, ATTN_SMEM);
    cudaFuncSetAttribute(attn_kernel<64>,
                         cudaFuncAttributeMaxDynamicSharedMemorySize, ATTN_SMEM);

    transpose_all<<<dim3(8, 8, 14), 256>>>(mlp1_w2, mlp2_w2, wq, wk, wv, wo, td_w, wt);

    const dim3 gemmBlk(256);
    const dim3 grid256x2(2, RTOT / 128, 2);  // batched pair, Nout=256
    const dim3 grid256(2, RTOT / 128, 1);
    const dim3 grid512(4, RTOT / 128, 1);

    for (int blk = 0; blk < 2; blk++) {
        const int cs = (blk == 0) ? 16 : 64;
        const int i  = blk;
        const float* fin = (blk == 0) ? feat : fb;
        const size_t bOff = (size_t)i * 256;
        float* Wt0 = wt + (size_t)(i * 6) * SLOT;

        geom_hidden_kernel<<<RTOT / cs, 256>>>(
            pos, mlp1_w1 + (size_t)i * 4 * 256, mlp1_b1 + bOff,
            mlp2_w1 + (size_t)i * 6 * 256, mlp2_b1 + bOff, h1, h2, cs);

        // batched: z=0: hpos = h1@W0 + b + fin ; z=1: hgeo = h2@W1 + b + fin
        tc_gemm<<<grid256x2, gemmBlk, TC_SMEM_TOTAL>>>(h1, Wt0 + 0 * SLOT, mlp1_b2 + bOff, fin,
            hpos, nullptr, DIM, 0, 1.f, nullptr, nullptr, nullptr, nullptr,
            h2, Wt0 + 1 * SLOT, mlp2_b2 + bOff, hgeo);
        tc_gemm<<<grid512, gemmBlk, TC_SMEM_TOTAL>>>(hgeo, Wt0 + 2 * SLOT, nullptr, feat,
            qb, kb, DOUT, 4, 1.f / 16.f, nullptr, nullptr, nullptr, nullptr,
            nullptr, nullptr, nullptr, nullptr);
        tc_gemm<<<grid256, gemmBlk, TC_SMEM_TOTAL>>>(hpos, Wt0 + 4 * SLOT, nullptr, feat,
            vb, nullptr, DIM, 2, 1.f, nullptr, nullptr, nullptr, nullptr,
            nullptr, nullptr, nullptr, nullptr);

        if (cs == 16)
            attn_kernel<16><<<RTOT / 64, 256, ATTN_SMEM>>>(qb, kb, vb, sb);
        else
            attn_kernel<64><<<RTOT / 64, 256, ATTN_SMEM>>>(qb, kb, vb, sb);

        // fused: fb = LN(hpos + attn@wo + bo)
        tc_gemm_ln<<<dim3(1, RTOT / 64), gemmBlk, LN_SMEM_TOTAL>>>(
            sb, Wt0 + 5 * SLOT, bo + bOff, hpos, fb, ln_g + bOff, ln_b + bOff);
    }

    tc_gemm<<<grid512, gemmBlk, TC_SMEM_TOTAL>>>(fb, wt + 12 * SLOT, td_b, feat,
        g512, nullptr, DOUT, 3, 1.f, bn_g, bn_b, bn_mean, bn_var,
        nullptr, nullptr, nullptr, nullptr);

    float* outp = (float*)d_out;
    knn_max_kernel<<<BATCH * MPTS, 128>>>(g512, knn, pos, fps,
                                          outp, outp + BATCH * MPTS * 3);
}